// round 13
// baseline (speedup 1.0000x reference)
#include <cuda_runtime.h>
#include <cuda_bf16.h>
#include <cstdint>

#define B_SZ   1024
#define DIN    1024
#define DHID   2048
#define TOPK   64
#define NCLAUSE 64
#define NACT   8
#define WCAP   96
#define WDELTA 0.04f
#define TAU    1.3f
#define CAP    512

// ---------------- scratch (static device globals; no allocations) ----------
__device__ float  g_R[DHID * NCLAUSE];
__device__ double g_basep[NCLAUSE][4];         // partial base log-sums
__device__ float  g_alpha[DHID];
__device__ float  g_f0[DHID];
__device__ unsigned g_cnt[B_SZ];
__device__ unsigned g_cand[B_SZ * CAP];        // (col<<16) | bf16(z) ; 2 MB
__device__ __nv_bfloat16 g_xh[B_SZ * DIN];
__device__ __nv_bfloat16 g_wth[DHID * DIN];    // W^T hi, [n][k]
__device__ __nv_bfloat16 g_wtl[DHID * DIN];    // W^T lo

__device__ __forceinline__ float softplusf_(float x) {
    return (x > 0.f) ? (x + log1pf(expf(-x))) : log1pf(expf(x));
}
__device__ __forceinline__ float b2f(unsigned short u) {
    __nv_bfloat16_raw r; r.x = u;
    return __bfloat162float(__nv_bfloat16(r));
}
__device__ __forceinline__ unsigned short f2bbits(float v) {
    __nv_bfloat16 h = __float2bfloat16(v);
    __nv_bfloat16_raw r = *(__nv_bfloat16_raw*)&h;
    return r.x;
}
__device__ __forceinline__ uint32_t smem_to_u32(const void* p) {
    uint32_t a;
    asm("{ .reg .u64 t; cvta.to.shared.u64 t, %1; cvt.u32.u64 %0, t; }" : "=r"(a) : "l"(p));
    return a;
}
#define SWZ(b) ((b) ^ (((b) >> 3) & 0x70))
#define CP_ASYNC16(s, g) asm volatile("cp.async.cg.shared.global [%0], [%1], 16;" :: "r"(s), "l"(g))
#define CP_COMMIT()      asm volatile("cp.async.commit_group;" ::: "memory")
#define CP_WAIT(n)       asm volatile("cp.async.wait_group %0;" :: "n"(n) : "memory")

__device__ __forceinline__ void ldsm_x4(uint32_t& r0, uint32_t& r1, uint32_t& r2, uint32_t& r3,
                                        uint32_t addr) {
    asm volatile("ldmatrix.sync.aligned.m8n8.x4.shared.b16 {%0,%1,%2,%3}, [%4];"
                 : "=r"(r0), "=r"(r1), "=r"(r2), "=r"(r3) : "r"(addr));
}
__device__ __forceinline__ void mma16816(float* c, const uint32_t* a, uint32_t b0, uint32_t b1) {
    asm volatile("mma.sync.aligned.m16n8k16.row.col.f32.bf16.bf16.f32 "
                 "{%0,%1,%2,%3}, {%4,%5,%6,%7}, {%8,%9}, {%0,%1,%2,%3};"
                 : "+f"(c[0]), "+f"(c[1]), "+f"(c[2]), "+f"(c[3])
                 : "r"(a[0]), "r"(a[1]), "r"(a[2]), "r"(a[3]), "r"(b0), "r"(b1));
}

// =================== 1) convert + clause tables + cnt zero ==================
// grid 2305: [0,256) clause chunks | [256,1280) x | [1280,2304) W^T | 2304 zero
#define CONV_BLOCKS (256 + 1024 + 1024 + 1)
#define JCHUNK (DHID / 4)

__global__ void __launch_bounds__(256) convert_kernel(
    const float* __restrict__ x, const float* __restrict__ W,
    const float* __restrict__ w_pos, const float* __restrict__ w_neg,
    const float* __restrict__ log_alpha, const float* __restrict__ beta) {
    int blk = blockIdx.x;
    int t   = threadIdx.x;

    if (blk < 256) {                        // ---- clause tables, 4 chunks/clause ----
        __shared__ double sred[256];
        int c     = blk >> 2;
        int chunk = blk & 3;
        int j0    = chunk * JCHUNK;
        double lsum = 0.0;
#pragma unroll
        for (int q = 0; q < JCHUNK / 256; q++) {
            int j = j0 + q * 256 + t;
            float wp = w_pos[c * DHID + j];
            float wn = w_neg[c * DHID + j];
            float m  = fmaxf(fmaxf(wp, wn), 0.f);
            float ep = expf(wp - m), en = expf(wn - m), e0 = expf(-m);
            float S  = ep + en + e0;
            float p  = ep / S, n = en / S;
            float a  = p - n;
            float b  = 1.f - p;
            float al = softplusf_(log_alpha[j]) + 0.5f;
            float bt = beta[j];
            float f0 = 1.f / (1.f + expf(al * bt));
            float L0 = fmaf(a, f0, b) + 1e-8f;
            g_R[j * NCLAUSE + c] = a / L0;
            if (c == 0) { g_alpha[j] = al; g_f0[j] = f0; }
            lsum += (double)logf(L0);
        }
        sred[t] = lsum;
        __syncthreads();
        for (int s = 128; s > 0; s >>= 1) {
            if (t < s) sred[t] += sred[t + s];
            __syncthreads();
        }
        if (t == 0) g_basep[c][chunk] = sred[0];
        return;
    }
    if (blk < 1280) {                       // ---- convert x -> xh ----
        int i = ((blk - 256) * 256 + t) * 4;
        float4 v = *(const float4*)(x + i);
        __nv_bfloat162 hi0 = {__float2bfloat16(v.x), __float2bfloat16(v.y)};
        __nv_bfloat162 hi1 = {__float2bfloat16(v.z), __float2bfloat16(v.w)};
        *(__nv_bfloat162*)(g_xh + i)     = hi0;
        *(__nv_bfloat162*)(g_xh + i + 2) = hi1;
        return;
    }
    if (blk < 2304) {                       // ---- W -> W^T (hi, lo), 32n x 64k ----
        __shared__ float tile[64][33];
        int bb = blk - 1280;
        int n0 = (bb & 63) * 32, k0 = (bb >> 6) * 64;
        int w = t >> 5, lane = t & 31;
#pragma unroll
        for (int j = 0; j < 8; j++) {
            int k = w + j * 8;
            tile[k][lane] = W[(size_t)(k0 + k) * DHID + n0 + lane];
        }
        __syncthreads();
#pragma unroll
        for (int nn = 0; nn < 4; nn++) {
            int n = w + nn * 8;
            float a0 = tile[2 * lane][n];
            float a1 = tile[2 * lane + 1][n];
            __nv_bfloat16 h0 = __float2bfloat16(a0), h1 = __float2bfloat16(a1);
            __nv_bfloat162 hp = {h0, h1};
            __nv_bfloat162 lp = {__float2bfloat16(a0 - __bfloat162float(h0)),
                                 __float2bfloat16(a1 - __bfloat162float(h1))};
            size_t off = (size_t)(n0 + n) * DIN + k0 + 2 * lane;
            *(__nv_bfloat162*)(g_wth + off) = hp;
            *(__nv_bfloat162*)(g_wtl + off) = lp;
        }
        return;
    }
    {                                       // ---- zero per-row candidate counters ----
#pragma unroll
        for (int q = 0; q < 4; q++) g_cnt[q * 256 + t] = 0u;
    }
}

// =================== 2) mma.sync GEMM + candidate-list epilogue =============
#define BK 64
#define A_BYTES (128 * BK * 2)
#define B_BYTES (64 * BK * 2)
#define STAGE_BYTES (A_BYTES + B_BYTES)
#define NSTAGE 4
#define GEMM_SMEM (NSTAGE * STAGE_BYTES)   // 96 KB
#define NITER 16

__global__ void __launch_bounds__(256, 2) gemm_mma_kernel(const float* __restrict__ bias) {
    extern __shared__ char smem[];
    uint32_t sbase = smem_to_u32(smem);
    int t = threadIdx.x;
    int bn = blockIdx.x & 31, bm = blockIdx.x >> 5;
    int wid = t >> 5, lane = t & 31;
    int wm = (wid >> 1) * 32;
    int wn = (wid & 1) * 32;

    int arow[4], aunit[4]; uint32_t asoff[4];
#pragma unroll
    for (int u = 0; u < 4; u++) {
        int idx = u * 256 + t;
        arow[u] = idx >> 3; aunit[u] = idx & 7;
        asoff[u] = SWZ(arow[u] * 128 + aunit[u] * 16);
    }
    int brow[2], bunit[2]; uint32_t bsoff[2];
#pragma unroll
    for (int u = 0; u < 2; u++) {
        int idx = u * 256 + t;
        brow[u] = idx >> 3; bunit[u] = idx & 7;
        bsoff[u] = SWZ(brow[u] * 128 + bunit[u] * 16);
    }

    auto issue = [&](int it) {
        if (it < NITER) {
            int kc = it;
            uint32_t sa = sbase + (it & (NSTAGE - 1)) * STAGE_BYTES;
            uint32_t sb = sa + A_BYTES;
#pragma unroll
            for (int u = 0; u < 4; u++)
                CP_ASYNC16(sa + asoff[u],
                           g_xh + (size_t)(bm * 128 + arow[u]) * DIN + kc * 64 + aunit[u] * 8);
#pragma unroll
            for (int u = 0; u < 2; u++)
                CP_ASYNC16(sb + bsoff[u],
                           g_wth + (size_t)(bn * 64 + brow[u]) * DIN + kc * 64 + bunit[u] * 8);
        }
        CP_COMMIT();
    };

    float acc[2][4][4];
#pragma unroll
    for (int i = 0; i < 2; i++)
#pragma unroll
        for (int j = 0; j < 4; j++)
#pragma unroll
            for (int r = 0; r < 4; r++) acc[i][j][r] = 0.f;

    issue(0); issue(1); issue(2);

    int lrow = lane & 15;
    int lhi  = lane >> 4;

    for (int it = 0; it < NITER; it++) {
        CP_WAIT(2);
        __syncthreads();
        issue(it + 3);
        uint32_t sa = sbase + (it & (NSTAGE - 1)) * STAGE_BYTES;
        uint32_t sb = sa + A_BYTES;
#pragma unroll
        for (int ks = 0; ks < 4; ks++) {
            int unit = 2 * ks + lhi;
            uint32_t afr[2][4], bfr[2][4];
#pragma unroll
            for (int mi = 0; mi < 2; mi++)
                ldsm_x4(afr[mi][0], afr[mi][1], afr[mi][2], afr[mi][3],
                        sa + SWZ((wm + mi * 16 + lrow) * 128 + unit * 16));
#pragma unroll
            for (int nf = 0; nf < 2; nf++)
                ldsm_x4(bfr[nf][0], bfr[nf][1], bfr[nf][2], bfr[nf][3],
                        sb + SWZ((wn + nf * 16 + lrow) * 128 + unit * 16));
#pragma unroll
            for (int mi = 0; mi < 2; mi++)
#pragma unroll
                for (int nf = 0; nf < 2; nf++) {
                    mma16816(acc[mi][nf * 2 + 0], afr[mi], bfr[nf][0], bfr[nf][2]);
                    mma16816(acc[mi][nf * 2 + 1], afr[mi], bfr[nf][1], bfr[nf][3]);
                }
        }
    }

    // epilogue: bias + relu -> per-row candidate list (v > TAU only)
    int qrow = lane >> 2;
    int qcol = (lane & 3) * 2;
#pragma unroll
    for (int mi = 0; mi < 2; mi++) {
#pragma unroll
        for (int nj = 0; nj < 4; nj++) {
            int col = bn * 64 + wn + nj * 8 + qcol;
            float b0 = bias[col], b1 = bias[col + 1];
            int r0 = bm * 128 + wm + mi * 16 + qrow;
            float v00 = fmaxf(acc[mi][nj][0] + b0, 0.f);
            float v01 = fmaxf(acc[mi][nj][1] + b1, 0.f);
            float v10 = fmaxf(acc[mi][nj][2] + b0, 0.f);
            float v11 = fmaxf(acc[mi][nj][3] + b1, 0.f);
            if (v00 > TAU) {
                unsigned p = atomicAdd(&g_cnt[r0], 1u);
                if (p < CAP) g_cand[r0 * CAP + p] = ((unsigned)col << 16) | f2bbits(v00);
            }
            if (v01 > TAU) {
                unsigned p = atomicAdd(&g_cnt[r0], 1u);
                if (p < CAP) g_cand[r0 * CAP + p] = ((unsigned)(col + 1) << 16) | f2bbits(v01);
            }
            if (v10 > TAU) {
                unsigned p = atomicAdd(&g_cnt[r0 + 8], 1u);
                if (p < CAP) g_cand[(r0 + 8) * CAP + p] = ((unsigned)col << 16) | f2bbits(v10);
            }
            if (v11 > TAU) {
                unsigned p = atomicAdd(&g_cnt[r0 + 8], 1u);
                if (p < CAP) g_cand[(r0 + 8) * CAP + p] = ((unsigned)(col + 1) << 16) | f2bbits(v11);
            }
        }
    }
}

// =================== 3) topk over candidate list + refine + correction ======
__global__ void __launch_bounds__(256) topk_corr_kernel(
    const float* __restrict__ x,
    const float* __restrict__ beta, const float* __restrict__ bias,
    const float* __restrict__ clause_weight, float* __restrict__ out) {
    __shared__ unsigned scand[CAP];
    __shared__ unsigned hist[256];
    __shared__ unsigned sh_d, sh_before;
    __shared__ unsigned cntA, cntW;
    __shared__ int    sidx[TOPK];
    __shared__ float  sg[TOPK];
    __shared__ float  part[256];
    __shared__ double cl[NCLAUSE];
    __shared__ int    widx[WCAP];
    __shared__ float  zwin[WCAP];
    __shared__ float  sxf[DIN];
    int row = blockIdx.x;
    int t   = threadIdx.x;
    int wid = t >> 5, lane = t & 31;

    unsigned cnt = g_cnt[row];
    if (cnt > CAP) cnt = CAP;
    for (unsigned i = t; i < cnt; i += 256)
        scand[i] = g_cand[row * CAP + i];
    ((float4*)sxf)[t] = ((const float4*)(x + (size_t)row * DIN))[t];
    if (t == 0) { cntA = 0; cntW = 0; }

    // ---- 2-level radix select over candidates (R10 logic, bound = cnt) ----
    unsigned prefix = 0, pmask = 0;
    int need = TOPK;
#pragma unroll
    for (int lvl = 0; lvl < 2; lvl++) {
        int shift = 8 - lvl * 8;
        hist[t] = 0;
        __syncthreads();
        for (unsigned i = t; i < cnt; i += 256) {
            unsigned b = scand[i] & 0xffffu;
            if ((b & pmask) == prefix) atomicAdd(&hist[(b >> shift) & 255u], 1u);
        }
        __syncthreads();
#pragma unroll
        for (int s = 1; s < 256; s <<= 1) {
            unsigned v = (t + s < 256) ? hist[t + s] : 0u;
            __syncthreads();
            hist[t] += v;
            __syncthreads();
        }
        unsigned nxt = (t == 255) ? 0u : hist[t + 1];
        if (hist[t] >= (unsigned)need && nxt < (unsigned)need) {
            sh_d = (unsigned)t;
            sh_before = nxt;
        }
        __syncthreads();
        need  -= (int)sh_before;
        prefix |= (sh_d << shift);
        pmask  |= (255u << shift);
        __syncthreads();
    }
    float Tf  = b2f((unsigned short)prefix);
    float whi = Tf + WDELTA, wlo = Tf - WDELTA;

    // ---- classify candidates: safe vs boundary window ----
    for (unsigned i = t; i < cnt; i += 256) {
        unsigned pk = scand[i];
        float za = b2f((unsigned short)(pk & 0xffffu));
        int j = (int)(pk >> 16);
        if (za > whi) {
            int pos = (int)atomicAdd(&cntA, 1u);
            float al = g_alpha[j];
            float f  = 1.f / (1.f + expf(-al * (za - beta[j])));
            sidx[pos] = j;
            sg[pos]   = f - g_f0[j];
        } else if (za >= wlo) {
            unsigned w = atomicAdd(&cntW, 1u);
            if (w < WCAP) widx[w] = j;
        }
    }
    __syncthreads();
    int A = (int)cntA;
    int W = (int)cntW; if (W > WCAP) W = WCAP;
    int need2 = TOPK - A;

    // ---- exact z for window: fp32 x * (wh + wl), warp per candidate ----
    for (int w = wid; w < W; w += 8) {
        int j = widx[w];
        const __nv_bfloat162* wh2 = (const __nv_bfloat162*)(g_wth + (size_t)j * DIN);
        const __nv_bfloat162* wl2 = (const __nv_bfloat162*)(g_wtl + (size_t)j * DIN);
        float s = 0.f;
        for (int p = lane; p < DIN / 2; p += 32) {
            __nv_bfloat162 b = wh2[p], d = wl2[p];
            float w0 = __bfloat162float(b.x) + __bfloat162float(d.x);
            float w1 = __bfloat162float(b.y) + __bfloat162float(d.y);
            s = fmaf(sxf[2 * p], w0, s);
            s = fmaf(sxf[2 * p + 1], w1, s);
        }
#pragma unroll
        for (int o = 16; o > 0; o >>= 1) s += __shfl_xor_sync(0xFFFFFFFFu, s, o);
        if (lane == 0) zwin[w] = fmaxf(s + bias[j], 0.f);
    }
    __syncthreads();

    // ---- exact re-rank of window ----
    if (t < W) {
        float zk = zwin[t]; int jk = widx[t];
        int rho = 0;
        for (int m = 0; m < W; m++) {
            float zm = zwin[m];
            if (zm > zk || (zm == zk && widx[m] < jk)) rho++;
        }
        if (rho < need2) {
            float al = g_alpha[jk];
            float f  = 1.f / (1.f + expf(-al * (zk - beta[jk])));
            sidx[A + rho] = jk;
            sg[A + rho]   = f - g_f0[jk];
        }
    }
    __syncthreads();

    // ---- clause correction (log1p series) + fp64 epilogue ----
    int c = t & 63;
    int grp = t >> 6;
    float acc = 0.f;
#pragma unroll
    for (int k0 = 0; k0 < TOPK; k0 += 4) {
        int k = k0 + grp;
        float u = g_R[sidx[k] * NCLAUSE + c] * sg[k];
        acc += u * fmaf(u, fmaf(u, 0.33333333f, -0.5f), 1.f);
    }
    part[t] = acc;
    __syncthreads();
    if (t < NCLAUSE) {
        float d = part[t] + part[t + 64] + part[t + 128] + part[t + 192];
        double base = (g_basep[t][0] + g_basep[t][1]) + (g_basep[t][2] + g_basep[t][3]);
        double logit = base + (double)d + (double)clause_weight[t];
        cl[t] = 1.0 / (1.0 + exp(-logit));
    }
    __syncthreads();
    if (t < NACT) {
        double s = 0.0;
#pragma unroll
        for (int l = 0; l < 8; l++) s += cl[t * 8 + l];
        out[row * NACT + t] = (float)s;
    }
}

// =================== launch =================================================
extern "C" void kernel_launch(void* const* d_in, const int* in_sizes, int n_in,
                              void* d_out, int out_size) {
    const float* x         = (const float*)d_in[0];
    const float* W_enc     = (const float*)d_in[1];
    const float* b_enc     = (const float*)d_in[2];
    const float* log_alpha = (const float*)d_in[3];
    const float* beta      = (const float*)d_in[4];
    const float* w_pos     = (const float*)d_in[5];
    const float* w_neg     = (const float*)d_in[6];
    const float* cw        = (const float*)d_in[7];
    float* out = (float*)d_out;

    static bool attr_set = false;
    if (!attr_set) {
        cudaFuncSetAttribute(gemm_mma_kernel,
                             cudaFuncAttributeMaxDynamicSharedMemorySize, GEMM_SMEM);
        attr_set = true;
    }

    convert_kernel<<<CONV_BLOCKS, 256>>>(x, W_enc, w_pos, w_neg, log_alpha, beta);
    gemm_mma_kernel<<<256, 256, GEMM_SMEM>>>(b_enc);
    topk_corr_kernel<<<B_SZ, 256>>>(x, beta, b_enc, cw, out);
}

// round 15
// speedup vs baseline: 1.2187x; 1.2187x over previous
#include <cuda_runtime.h>
#include <cuda_bf16.h>
#include <cstdint>

#define B_SZ   1024
#define DIN    1024
#define DHID   2048
#define TOPK   64
#define NCLAUSE 64
#define NACT   8
#define WCAP   96
#define WDELTA 0.04f
#define LCAP   640
#define TAUB   0x3F80u   // bf16 bits of 1.0f

// ---------------- scratch (static device globals; no allocations) ----------
__device__ __nv_bfloat16 g_zb[B_SZ * DHID];    // approx relu(x@W+b), bf16
__device__ float  g_R[DHID * NCLAUSE];
__device__ double g_basep[NCLAUSE][4];         // partial base log-sums
__device__ float  g_alpha[DHID];
__device__ float  g_f0[DHID];
__device__ __nv_bfloat16 g_xh[B_SZ * DIN];
__device__ __nv_bfloat16 g_wth[DHID * DIN];    // W^T hi, [n][k]
__device__ __nv_bfloat16 g_wtl[DHID * DIN];    // W^T lo

__device__ __forceinline__ float softplusf_(float x) {
    return (x > 0.f) ? (x + log1pf(expf(-x))) : log1pf(expf(x));
}
__device__ __forceinline__ float b2f(unsigned short u) {
    __nv_bfloat16_raw r; r.x = u;
    return __bfloat162float(__nv_bfloat16(r));
}
__device__ __forceinline__ uint32_t smem_to_u32(const void* p) {
    uint32_t a;
    asm("{ .reg .u64 t; cvta.to.shared.u64 t, %1; cvt.u32.u64 %0, t; }" : "=r"(a) : "l"(p));
    return a;
}
#define SWZ(b) ((b) ^ (((b) >> 3) & 0x70))
#define CP_ASYNC16(s, g) asm volatile("cp.async.cg.shared.global [%0], [%1], 16;" :: "r"(s), "l"(g))
#define CP_COMMIT()      asm volatile("cp.async.commit_group;" ::: "memory")
#define CP_WAIT(n)       asm volatile("cp.async.wait_group %0;" :: "n"(n) : "memory")

__device__ __forceinline__ void ldsm_x4(uint32_t& r0, uint32_t& r1, uint32_t& r2, uint32_t& r3,
                                        uint32_t addr) {
    asm volatile("ldmatrix.sync.aligned.m8n8.x4.shared.b16 {%0,%1,%2,%3}, [%4];"
                 : "=r"(r0), "=r"(r1), "=r"(r2), "=r"(r3) : "r"(addr));
}
__device__ __forceinline__ void mma16816(float* c, const uint32_t* a, uint32_t b0, uint32_t b1) {
    asm volatile("mma.sync.aligned.m16n8k16.row.col.f32.bf16.bf16.f32 "
                 "{%0,%1,%2,%3}, {%4,%5,%6,%7}, {%8,%9}, {%0,%1,%2,%3};"
                 : "+f"(c[0]), "+f"(c[1]), "+f"(c[2]), "+f"(c[3])
                 : "r"(a[0]), "r"(a[1]), "r"(a[2]), "r"(a[3]), "r"(b0), "r"(b1));
}

// =================== 1) convert + clause tables (R10 winner, unchanged) =====
#define CONV_BLOCKS (256 + 1024 + 1024)
#define JCHUNK (DHID / 4)

__global__ void __launch_bounds__(256) convert_kernel(
    const float* __restrict__ x, const float* __restrict__ W,
    const float* __restrict__ w_pos, const float* __restrict__ w_neg,
    const float* __restrict__ log_alpha, const float* __restrict__ beta) {
    int blk = blockIdx.x;
    int t   = threadIdx.x;

    if (blk < 256) {                        // ---- clause tables, 4 chunks/clause ----
        __shared__ double sred[256];
        int c     = blk >> 2;
        int chunk = blk & 3;
        int j0    = chunk * JCHUNK;
        double lsum = 0.0;
#pragma unroll
        for (int q = 0; q < JCHUNK / 256; q++) {
            int j = j0 + q * 256 + t;
            float wp = w_pos[c * DHID + j];
            float wn = w_neg[c * DHID + j];
            float m  = fmaxf(fmaxf(wp, wn), 0.f);
            float ep = expf(wp - m), en = expf(wn - m), e0 = expf(-m);
            float S  = ep + en + e0;
            float p  = ep / S, n = en / S;
            float a  = p - n;
            float b  = 1.f - p;
            float al = softplusf_(log_alpha[j]) + 0.5f;
            float bt = beta[j];
            float f0 = 1.f / (1.f + expf(al * bt));
            float L0 = fmaf(a, f0, b) + 1e-8f;
            g_R[j * NCLAUSE + c] = a / L0;
            if (c == 0) { g_alpha[j] = al; g_f0[j] = f0; }
            lsum += (double)logf(L0);
        }
        sred[t] = lsum;
        __syncthreads();
        for (int s = 128; s > 0; s >>= 1) {
            if (t < s) sred[t] += sred[t + s];
            __syncthreads();
        }
        if (t == 0) g_basep[c][chunk] = sred[0];
        return;
    }
    if (blk < 1280) {                       // ---- convert x -> xh ----
        int i = ((blk - 256) * 256 + t) * 4;
        float4 v = *(const float4*)(x + i);
        __nv_bfloat162 hi0 = {__float2bfloat16(v.x), __float2bfloat16(v.y)};
        __nv_bfloat162 hi1 = {__float2bfloat16(v.z), __float2bfloat16(v.w)};
        *(__nv_bfloat162*)(g_xh + i)     = hi0;
        *(__nv_bfloat162*)(g_xh + i + 2) = hi1;
        return;
    }
    {                                       // ---- W -> W^T (hi, lo), 32n x 64k ----
        __shared__ float tile[64][33];
        int bb = blk - 1280;
        int n0 = (bb & 63) * 32, k0 = (bb >> 6) * 64;
        int w = t >> 5, lane = t & 31;
#pragma unroll
        for (int j = 0; j < 8; j++) {
            int k = w + j * 8;
            tile[k][lane] = W[(size_t)(k0 + k) * DHID + n0 + lane];
        }
        __syncthreads();
#pragma unroll
        for (int nn = 0; nn < 4; nn++) {
            int n = w + nn * 8;
            float a0 = tile[2 * lane][n];
            float a1 = tile[2 * lane + 1][n];
            __nv_bfloat16 h0 = __float2bfloat16(a0), h1 = __float2bfloat16(a1);
            __nv_bfloat162 hp = {h0, h1};
            __nv_bfloat162 lp = {__float2bfloat16(a0 - __bfloat162float(h0)),
                                 __float2bfloat16(a1 - __bfloat162float(h1))};
            size_t off = (size_t)(n0 + n) * DIN + k0 + 2 * lane;
            *(__nv_bfloat162*)(g_wth + off) = hp;
            *(__nv_bfloat162*)(g_wtl + off) = lp;
        }
    }
}

// =================== 2) mma.sync GEMM (R10 winner, unchanged) ===============
#define BK 64
#define A_BYTES (128 * BK * 2)
#define B_BYTES (64 * BK * 2)
#define STAGE_BYTES (A_BYTES + B_BYTES)
#define NSTAGE 4
#define GEMM_SMEM (NSTAGE * STAGE_BYTES)   // 96 KB
#define NITER 16

__global__ void __launch_bounds__(256, 2) gemm_mma_kernel(const float* __restrict__ bias) {
    extern __shared__ char smem[];
    uint32_t sbase = smem_to_u32(smem);
    int t = threadIdx.x;
    int bn = blockIdx.x & 31, bm = blockIdx.x >> 5;
    int wid = t >> 5, lane = t & 31;
    int wm = (wid >> 1) * 32;
    int wn = (wid & 1) * 32;

    int arow[4], aunit[4]; uint32_t asoff[4];
#pragma unroll
    for (int u = 0; u < 4; u++) {
        int idx = u * 256 + t;
        arow[u] = idx >> 3; aunit[u] = idx & 7;
        asoff[u] = SWZ(arow[u] * 128 + aunit[u] * 16);
    }
    int brow[2], bunit[2]; uint32_t bsoff[2];
#pragma unroll
    for (int u = 0; u < 2; u++) {
        int idx = u * 256 + t;
        brow[u] = idx >> 3; bunit[u] = idx & 7;
        bsoff[u] = SWZ(brow[u] * 128 + bunit[u] * 16);
    }

    auto issue = [&](int it) {
        if (it < NITER) {
            int kc = it;
            uint32_t sa = sbase + (it & (NSTAGE - 1)) * STAGE_BYTES;
            uint32_t sb = sa + A_BYTES;
#pragma unroll
            for (int u = 0; u < 4; u++)
                CP_ASYNC16(sa + asoff[u],
                           g_xh + (size_t)(bm * 128 + arow[u]) * DIN + kc * 64 + aunit[u] * 8);
#pragma unroll
            for (int u = 0; u < 2; u++)
                CP_ASYNC16(sb + bsoff[u],
                           g_wth + (size_t)(bn * 64 + brow[u]) * DIN + kc * 64 + bunit[u] * 8);
        }
        CP_COMMIT();
    };

    float acc[2][4][4];
#pragma unroll
    for (int i = 0; i < 2; i++)
#pragma unroll
        for (int j = 0; j < 4; j++)
#pragma unroll
            for (int r = 0; r < 4; r++) acc[i][j][r] = 0.f;

    issue(0); issue(1); issue(2);

    int lrow = lane & 15;
    int lhi  = lane >> 4;

    for (int it = 0; it < NITER; it++) {
        CP_WAIT(2);
        __syncthreads();
        issue(it + 3);
        uint32_t sa = sbase + (it & (NSTAGE - 1)) * STAGE_BYTES;
        uint32_t sb = sa + A_BYTES;
#pragma unroll
        for (int ks = 0; ks < 4; ks++) {
            int unit = 2 * ks + lhi;
            uint32_t afr[2][4], bfr[2][4];
#pragma unroll
            for (int mi = 0; mi < 2; mi++)
                ldsm_x4(afr[mi][0], afr[mi][1], afr[mi][2], afr[mi][3],
                        sa + SWZ((wm + mi * 16 + lrow) * 128 + unit * 16));
#pragma unroll
            for (int nf = 0; nf < 2; nf++)
                ldsm_x4(bfr[nf][0], bfr[nf][1], bfr[nf][2], bfr[nf][3],
                        sb + SWZ((wn + nf * 16 + lrow) * 128 + unit * 16));
#pragma unroll
            for (int mi = 0; mi < 2; mi++)
#pragma unroll
                for (int nf = 0; nf < 2; nf++) {
                    mma16816(acc[mi][nf * 2 + 0], afr[mi], bfr[nf][0], bfr[nf][2]);
                    mma16816(acc[mi][nf * 2 + 1], afr[mi], bfr[nf][1], bfr[nf][3]);
                }
        }
    }

    int qrow = lane >> 2;
    int qcol = (lane & 3) * 2;
#pragma unroll
    for (int mi = 0; mi < 2; mi++) {
#pragma unroll
        for (int nj = 0; nj < 4; nj++) {
            int col = bn * 64 + wn + nj * 8 + qcol;
            float b0 = bias[col], b1 = bias[col + 1];
            int r0 = bm * 128 + wm + mi * 16 + qrow;
            __nv_bfloat162 p0, p1;
            p0.x = __float2bfloat16(fmaxf(acc[mi][nj][0] + b0, 0.f));
            p0.y = __float2bfloat16(fmaxf(acc[mi][nj][1] + b1, 0.f));
            p1.x = __float2bfloat16(fmaxf(acc[mi][nj][2] + b0, 0.f));
            p1.y = __float2bfloat16(fmaxf(acc[mi][nj][3] + b1, 0.f));
            *(__nv_bfloat162*)&g_zb[(size_t)r0 * DHID + col]       = p0;
            *(__nv_bfloat162*)&g_zb[(size_t)(r0 + 8) * DHID + col] = p1;
        }
    }
}

// =================== 3) topk: in-kernel candidate list + guarded fallback ===
__global__ void __launch_bounds__(256) topk_corr_kernel(
    const float* __restrict__ x,
    const float* __restrict__ beta, const float* __restrict__ bias,
    const float* __restrict__ clause_weight, float* __restrict__ out) {
    __shared__ __align__(16) unsigned short sbits[DHID];   // full row (fallback)
    __shared__ __align__(16) float sxf[DIN];               // fp32 x row
    __shared__ unsigned list[LCAP];            // (col<<16) | bits, z >= 1.0
    __shared__ unsigned hist[256];
    __shared__ unsigned sh_d, sh_before;
    __shared__ unsigned cntL, cntA, cntW;
    __shared__ int    sidx[TOPK];
    __shared__ float  sg[TOPK];
    __shared__ float  part[256];
    __shared__ double cl[NCLAUSE];
    __shared__ int    widx[WCAP];
    __shared__ float  zwin[WCAP];
    int row = blockIdx.x;
    int t   = threadIdx.x;
    int wid = t >> 5, lane = t & 31;

    unsigned short zs[8];
    {
        uint4 v = ((const uint4*)(g_zb + (size_t)row * DHID))[t];
        ((uint4*)sbits)[t] = v;
        zs[0] = (unsigned short)(v.x & 0xffffu); zs[1] = (unsigned short)(v.x >> 16);
        zs[2] = (unsigned short)(v.y & 0xffffu); zs[3] = (unsigned short)(v.y >> 16);
        zs[4] = (unsigned short)(v.z & 0xffffu); zs[5] = (unsigned short)(v.z >> 16);
        zs[6] = (unsigned short)(v.w & 0xffffu); zs[7] = (unsigned short)(v.w >> 16);
        ((float4*)sxf)[t] = ((const float4*)(x + (size_t)row * DIN))[t];
    }
    if (t == 0) { cntL = 0; cntA = 0; cntW = 0; }
    __syncthreads();

    // ---- build candidate list: all elements with z >= 1.0 (bits compare) ----
#pragma unroll
    for (int e = 0; e < 8; e++) {
        unsigned b = (unsigned)zs[e];
        if (b >= TAUB) {
            unsigned p = atomicAdd(&cntL, 1u);
            if (p < LCAP) list[p] = ((unsigned)(t * 8 + e) << 16) | b;
        }
    }
    __syncthreads();
    unsigned cnt = cntL;
    bool fast = (cnt >= (unsigned)TOPK && cnt <= (unsigned)LCAP);

    // ---- radix select for Tf: over list (fast) or full row (fallback) ----
    unsigned prefix = 0, pmask = 0;
    int need = TOPK;
    if (fast) {
        for (int lvl = 0; lvl < 2; lvl++) {
            int shift = 8 - lvl * 8;
            hist[t] = 0;
            __syncthreads();
            for (unsigned i = t; i < cnt; i += 256) {
                unsigned b = list[i] & 0xffffu;
                if ((b & pmask) == prefix) atomicAdd(&hist[(b >> shift) & 255u], 1u);
            }
            __syncthreads();
#pragma unroll
            for (int s = 1; s < 256; s <<= 1) {
                unsigned v = (t + s < 256) ? hist[t + s] : 0u;
                __syncthreads();
                hist[t] += v;
                __syncthreads();
            }
            unsigned nxt = (t == 255) ? 0u : hist[t + 1];
            if (hist[t] >= (unsigned)need && nxt < (unsigned)need) {
                sh_d = (unsigned)t; sh_before = nxt;
            }
            __syncthreads();
            need  -= (int)sh_before;
            prefix |= (sh_d << shift);
            pmask  |= (255u << shift);
            __syncthreads();
        }
        // window must lie entirely above the list threshold (1.0)
        if (b2f((unsigned short)prefix) - WDELTA < 1.0f) fast = false;
    }
    if (!fast) {                            // ---- fallback: R10 full-row radix ----
        prefix = 0; pmask = 0; need = TOPK;
        for (int lvl = 0; lvl < 2; lvl++) {
            int shift = 8 - lvl * 8;
            hist[t] = 0;
            __syncthreads();
            for (int i = t; i < DHID; i += 256) {
                unsigned b = sbits[i];
                if ((b & pmask) == prefix) atomicAdd(&hist[(b >> shift) & 255u], 1u);
            }
            __syncthreads();
#pragma unroll
            for (int s = 1; s < 256; s <<= 1) {
                unsigned v = (t + s < 256) ? hist[t + s] : 0u;
                __syncthreads();
                hist[t] += v;
                __syncthreads();
            }
            unsigned nxt = (t == 255) ? 0u : hist[t + 1];
            if (hist[t] >= (unsigned)need && nxt < (unsigned)need) {
                sh_d = (unsigned)t; sh_before = nxt;
            }
            __syncthreads();
            need  -= (int)sh_before;
            prefix |= (sh_d << shift);
            pmask  |= (255u << shift);
            __syncthreads();
        }
    }
    float Tf  = b2f((unsigned short)prefix);
    float whi = Tf + WDELTA, wlo = Tf - WDELTA;

    // ---- classify: safe vs boundary window ----
    if (fast) {
        for (unsigned i = t; i < cnt; i += 256) {
            unsigned pk = list[i];
            float za = b2f((unsigned short)(pk & 0xffffu));
            int j = (int)(pk >> 16);
            if (za > whi) {
                int pos = (int)atomicAdd(&cntA, 1u);
                float al = g_alpha[j];
                float f  = 1.f / (1.f + expf(-al * (za - beta[j])));
                sidx[pos] = j;
                sg[pos]   = f - g_f0[j];
            } else if (za >= wlo) {
                unsigned w = atomicAdd(&cntW, 1u);
                if (w < WCAP) widx[w] = j;
            }
        }
    } else {
        for (int i = t; i < DHID; i += 256) {
            float za = b2f(sbits[i]);
            if (za > whi) {
                int pos = (int)atomicAdd(&cntA, 1u);
                float al = g_alpha[i];
                float f  = 1.f / (1.f + expf(-al * (za - beta[i])));
                sidx[pos] = i;
                sg[pos]   = f - g_f0[i];
            } else if (za >= wlo) {
                unsigned w = atomicAdd(&cntW, 1u);
                if (w < WCAP) widx[w] = i;
            }
        }
    }
    __syncthreads();
    int A = (int)cntA;
    int W = (int)cntW; if (W > WCAP) W = WCAP;
    int need2 = TOPK - A;

    // ---- exact z for window: fp32 x * (wh + wl), warp per candidate ----
    for (int w = wid; w < W; w += 8) {
        int j = widx[w];
        const __nv_bfloat162* wh2 = (const __nv_bfloat162*)(g_wth + (size_t)j * DIN);
        const __nv_bfloat162* wl2 = (const __nv_bfloat162*)(g_wtl + (size_t)j * DIN);
        float s = 0.f;
        for (int p = lane; p < DIN / 2; p += 32) {
            __nv_bfloat162 b = wh2[p], d = wl2[p];
            float w0 = __bfloat162float(b.x) + __bfloat162float(d.x);
            float w1 = __bfloat162float(b.y) + __bfloat162float(d.y);
            s = fmaf(sxf[2 * p], w0, s);
            s = fmaf(sxf[2 * p + 1], w1, s);
        }
#pragma unroll
        for (int o = 16; o > 0; o >>= 1) s += __shfl_xor_sync(0xFFFFFFFFu, s, o);
        if (lane == 0) zwin[w] = fmaxf(s + bias[j], 0.f);
    }
    __syncthreads();

    // ---- exact re-rank of window ----
    if (t < W) {
        float zk = zwin[t]; int jk = widx[t];
        int rho = 0;
        for (int m = 0; m < W; m++) {
            float zm = zwin[m];
            if (zm > zk || (zm == zk && widx[m] < jk)) rho++;
        }
        if (rho < need2) {
            float al = g_alpha[jk];
            float f  = 1.f / (1.f + expf(-al * (zk - beta[jk])));
            sidx[A + rho] = jk;
            sg[A + rho]   = f - g_f0[jk];
        }
    }
    __syncthreads();

    // ---- clause correction (log1p series) + fp64 epilogue ----
    int c = t & 63;
    int grp = t >> 6;
    float acc = 0.f;
#pragma unroll
    for (int k0 = 0; k0 < TOPK; k0 += 4) {
        int k = k0 + grp;
        float u = g_R[sidx[k] * NCLAUSE + c] * sg[k];
        acc += u * fmaf(u, fmaf(u, 0.33333333f, -0.5f), 1.f);
    }
    part[t] = acc;
    __syncthreads();
    if (t < NCLAUSE) {
        float d = part[t] + part[t + 64] + part[t + 128] + part[t + 192];
        double base = (g_basep[t][0] + g_basep[t][1]) + (g_basep[t][2] + g_basep[t][3]);
        double logit = base + (double)d + (double)clause_weight[t];
        cl[t] = 1.0 / (1.0 + exp(-logit));
    }
    __syncthreads();
    if (t < NACT) {
        double s = 0.0;
#pragma unroll
        for (int l = 0; l < 8; l++) s += cl[t * 8 + l];
        out[row * NACT + t] = (float)s;
    }
}

// =================== launch =================================================
extern "C" void kernel_launch(void* const* d_in, const int* in_sizes, int n_in,
                              void* d_out, int out_size) {
    const float* x         = (const float*)d_in[0];
    const float* W_enc     = (const float*)d_in[1];
    const float* b_enc     = (const float*)d_in[2];
    const float* log_alpha = (const float*)d_in[3];
    const float* beta      = (const float*)d_in[4];
    const float* w_pos     = (const float*)d_in[5];
    const float* w_neg     = (const float*)d_in[6];
    const float* cw        = (const float*)d_in[7];
    float* out = (float*)d_out;

    static bool attr_set = false;
    if (!attr_set) {
        cudaFuncSetAttribute(gemm_mma_kernel,
                             cudaFuncAttributeMaxDynamicSharedMemorySize, GEMM_SMEM);
        attr_set = true;
    }

    convert_kernel<<<CONV_BLOCKS, 256>>>(x, W_enc, w_pos, w_neg, log_alpha, beta);
    gemm_mma_kernel<<<256, 256, GEMM_SMEM>>>(b_enc);
    topk_corr_kernel<<<B_SZ, 256>>>(x, beta, b_enc, cw, out);
}